// round 12
// baseline (speedup 1.0000x reference)
#include <cuda_runtime.h>
#include <cuda_bf16.h>
#include <math.h>
#include <stdint.h>

#define Himg 56
#define Wimg 56
#define WS 7
#define SHIFT 3
#define HEADS 4
#define DIM 128
#define NTOK 49
#define NWIN 4096           // 64 imgs * 64 windows
#define MTOK 200704         // NWIN * NTOK
#define HD 32

// ---------------- scratch (static device globals; no allocation) -------------
__device__ __nv_bfloat16 g_qkv [(size_t)MTOK * 3 * DIM];
__device__ __nv_bfloat16 g_attn[(size_t)MTOK * DIM];
__device__ float         g_x2  [(size_t)MTOK * DIM];
__device__ __nv_bfloat16 g_ln2 [(size_t)MTOK * DIM];
__device__ __nv_bfloat16 g_h   [(size_t)MTOK * 4 * DIM];
// transposed weights [N, K] in bf16
__device__ __nv_bfloat16 g_wt_qkv [384 * 128];
__device__ __nv_bfloat16 g_wt_proj[128 * 128];
__device__ __nv_bfloat16 g_wt1    [512 * 128];
__device__ __nv_bfloat16 g_wt2    [128 * 512];

__device__ __forceinline__ uint32_t smem_u32(const void* p) {
    uint32_t a;
    asm("{ .reg .u64 t; cvta.to.shared.u64 t, %1; cvt.u32.u64 %0, t; }" : "=r"(a) : "l"(p));
    return a;
}
__device__ __forceinline__ void cpa16(uint32_t dst, const void* src) {
    asm volatile("cp.async.cg.shared.global [%0], [%1], 16;" :: "r"(dst), "l"(src));
}
__device__ __forceinline__ int img_of(int wt) {
    int w = wt / NTOK, n = wt - w * NTOK;
    int bimg = w >> 6, wi = w & 63;
    int rr = (wi >> 3) * WS + n / WS;
    int cc = (wi & 7)  * WS + n % WS;
    int r = rr + SHIFT; if (r >= Himg) r -= Himg;
    int c = cc + SHIFT; if (c >= Wimg) c -= Wimg;
    return bimg * 3136 + r * 56 + c;
}

// ---------------- kernel 0: all 4 weight transposes fused ---------------------
__global__ void k_transpose_all(const float* __restrict__ qkv_w,
                                const float* __restrict__ proj_w,
                                const float* __restrict__ w1,
                                const float* __restrict__ w2) {
    int i = blockIdx.x * 256 + threadIdx.x;
    if (i < 49152) {
        int k = i / 384, n = i - k * 384;
        g_wt_qkv[n * 128 + k] = __float2bfloat16(qkv_w[i]);
    } else if (i < 65536) {
        int j = i - 49152;
        int k = j >> 7, n = j & 127;
        g_wt_proj[n * 128 + k] = __float2bfloat16(proj_w[j]);
    } else if (i < 131072) {
        int j = i - 65536;
        int k = j >> 9, n = j & 511;
        g_wt1[n * 128 + k] = __float2bfloat16(w1[j]);
    } else if (i < 196608) {
        int j = i - 131072;
        int k = j >> 7, n = j & 127;
        g_wt2[n * 512 + k] = __float2bfloat16(w2[j]);
    }
}

// ---- shared MMA pass macro: 128x128 output tile, K=128, over 8 k-steps ------
#define MMA_PASS(baseA, aR, baseB, bR, ACC)                                   \
    {                                                                         \
        _Pragma("unroll")                                                     \
        for (int ks = 0; ks < 8; ks++) {                                      \
            uint32_t kwb = (uint32_t)ks * 32;                                 \
            uint32_t a_[2][4], bb_[8][2];                                     \
            _Pragma("unroll")                                                 \
            for (int ma = 0; ma < 2; ma++)                                    \
                asm volatile(                                                 \
                    "ldmatrix.sync.aligned.m8n8.x4.shared.b16 {%0,%1,%2,%3}, [%4];" \
                    : "=r"(a_[ma][0]), "=r"(a_[ma][1]), "=r"(a_[ma][2]), "=r"(a_[ma][3]) \
                    : "r"((baseA) + aR[ma] + kwb));                           \
            _Pragma("unroll")                                                 \
            for (int np = 0; np < 4; np++)                                    \
                asm volatile(                                                 \
                    "ldmatrix.sync.aligned.m8n8.x4.shared.b16 {%0,%1,%2,%3}, [%4];" \
                    : "=r"(bb_[2*np][0]), "=r"(bb_[2*np][1]),                 \
                      "=r"(bb_[2*np+1][0]), "=r"(bb_[2*np+1][1])              \
                    : "r"((baseB) + bR[np] + kwb));                           \
            _Pragma("unroll")                                                 \
            for (int ma = 0; ma < 2; ma++)                                    \
                _Pragma("unroll")                                             \
                for (int na = 0; na < 8; na++)                                \
                    asm volatile(                                             \
                        "mma.sync.aligned.m16n8k16.row.col.f32.bf16.bf16.f32 " \
                        "{%0,%1,%2,%3}, {%4,%5,%6,%7}, {%8,%9}, {%0,%1,%2,%3};" \
                        : "+f"(ACC[ma][na][0]), "+f"(ACC[ma][na][1]),         \
                          "+f"(ACC[ma][na][2]), "+f"(ACC[ma][na][3])          \
                        : "r"(a_[ma][0]), "r"(a_[ma][1]), "r"(a_[ma][2]), "r"(a_[ma][3]), \
                          "r"(bb_[na][0]), "r"(bb_[na][1]));                  \
        }                                                                     \
    }

// ---- QKV GEMM with FUSED LN1 + shift + window-partition on the A path -------
template <int TPC>
__global__ void __launch_bounds__(256, 2)
k_qkv(const float* __restrict__ x, const __nv_bfloat16* __restrict__ BT,
      const float* __restrict__ bias,
      const float* __restrict__ gw, const float* __restrict__ gb,
      __nv_bfloat16* __restrict__ C) {
    constexpr int SR = 68;
    constexpr int TW = 128 * SR;
    constexpr int N = 384;
    extern __shared__ uint32_t dsm[];
    uint32_t sBu = smem_u32(dsm);              // B tile (resident)
    uint32_t* sA = dsm + TW;                   // A tile (LN-filled)
    uint32_t sAu = sBu + TW * 4;

    int tid = threadIdx.x;
    int wid = tid >> 5, lane = tid & 31;
    int wm = wid & 3, wn = wid >> 2;
    int n0 = blockIdx.x << 7;
    int mBase = blockIdx.y * (TPC * 128);
    int g = lane >> 2, cq = lane & 3;
    int mi = lane >> 3, l7 = lane & 7;

    {
        int ROWT = tid >> 1, HALF = tid & 1;
        const __nv_bfloat16* Bsrc = BT + (size_t)(n0 + ROWT) * 128 + HALF * 64;
        uint32_t Bdst = sBu + (ROWT * SR + HALF * 32) * 4;
        #pragma unroll
        for (int i = 0; i < 8; i++) cpa16(Bdst + i * 16, Bsrc + i * 8);
        asm volatile("cp.async.commit_group;" ::: "memory");
    }

    float4 w4 = *(const float4*)(gw + lane * 4);
    float4 b4 = *(const float4*)(gb + lane * 4);

    uint32_t aRow[2], bRow[4];
    #pragma unroll
    for (int ma = 0; ma < 2; ma++)
        aRow[ma] = (uint32_t)((wm * 32 + ma * 16 + ((mi & 1) << 3) + l7) * SR +
                              ((mi >> 1) << 2)) * 4;
    #pragma unroll
    for (int np = 0; np < 4; np++)
        bRow[np] = (uint32_t)((wn * 64 + np * 16 + ((mi >> 1) << 3) + l7) * SR +
                              ((mi & 1) << 2)) * 4;

    for (int t = 0; t < TPC; t++) {
        int m0 = mBase + t * 128;
        #pragma unroll
        for (int grp = 0; grp < 4; grp++) {
            float4 v[4];
            int rows[4];
            #pragma unroll
            for (int r = 0; r < 4; r++) {
                rows[r] = wid * 16 + grp * 4 + r;
                int img = img_of(m0 + rows[r]);
                v[r] = *(const float4*)(x + (size_t)img * DIM + lane * 4);
            }
            #pragma unroll
            for (int r = 0; r < 4; r++) {
                float sv = v[r].x + v[r].y + v[r].z + v[r].w;
                float sq = v[r].x * v[r].x + v[r].y * v[r].y +
                           v[r].z * v[r].z + v[r].w * v[r].w;
                #pragma unroll
                for (int o = 16; o > 0; o >>= 1) {
                    sv += __shfl_xor_sync(0xffffffffu, sv, o);
                    sq += __shfl_xor_sync(0xffffffffu, sq, o);
                }
                float mean = sv * (1.0f / 128.0f);
                float inv  = rsqrtf(sq * (1.0f / 128.0f) - mean * mean + 1e-5f);
                __nv_bfloat162 o0 = __floats2bfloat162_rn(
                    (v[r].x - mean) * inv * w4.x + b4.x,
                    (v[r].y - mean) * inv * w4.y + b4.y);
                __nv_bfloat162 o1 = __floats2bfloat162_rn(
                    (v[r].z - mean) * inv * w4.z + b4.z,
                    (v[r].w - mean) * inv * w4.w + b4.w);
                uint2 pk;
                pk.x = *reinterpret_cast<uint32_t*>(&o0);
                pk.y = *reinterpret_cast<uint32_t*>(&o1);
                *(uint2*)(sA + rows[r] * SR + lane * 2) = pk;
            }
        }
        if (t == 0)
            asm volatile("cp.async.wait_group 0;" ::: "memory");
        __syncthreads();

        float acc[2][8][4];
        #pragma unroll
        for (int i = 0; i < 2; i++)
            #pragma unroll
            for (int j = 0; j < 8; j++)
                #pragma unroll
                for (int q = 0; q < 4; q++) acc[i][j][q] = 0.0f;
        MMA_PASS(sAu, aRow, sBu, bRow, acc);

        #pragma unroll
        for (int ma = 0; ma < 2; ma++) {
            int r0 = m0 + wm * 32 + ma * 16 + g;
            #pragma unroll
            for (int na = 0; na < 8; na++) {
                int cb = n0 + wn * 64 + na * 8 + 2 * cq;
                float b0 = bias[cb], b1 = bias[cb + 1];
                *(__nv_bfloat162*)(C + (size_t)r0 * N + cb) =
                    __floats2bfloat162_rn(acc[ma][na][0] + b0, acc[ma][na][1] + b1);
                *(__nv_bfloat162*)(C + (size_t)(r0 + 8) * N + cb) =
                    __floats2bfloat162_rn(acc[ma][na][2] + b0, acc[ma][na][3] + b1);
            }
        }
        __syncthreads();
    }
}

// ---- M-tile-pipelined bf16 HMMA GEMM, K=128, B tile resident ----------------
// EPI: 1 = +bias, GELU (bf16 out);
//      3 = +bias +residual[x, scattered] + LN2 -> ln2 bf16 (Cout) + x2 fp32 (out2)
template <int EPI, int TPC>
__global__ void __launch_bounds__(256, 2)
k_bgemm_p(const __nv_bfloat16* __restrict__ A, const __nv_bfloat16* __restrict__ BT,
          const float* __restrict__ bias, const float* __restrict__ res,
          void* __restrict__ Cout, int N,
          const float* __restrict__ lnw, const float* __restrict__ lnb,
          float* __restrict__ out2) {
    constexpr int SR = 68;                     // words per smem row
    constexpr int TW = 128 * SR;
    extern __shared__ uint32_t dsm[];
    uint32_t sBu = smem_u32(dsm);              // B tile (resident)
    uint32_t sAu = sBu + TW * 4;               // A tiles (double buffer)
    float* redS = (float*)(dsm + 3 * TW);
    float* redQ = redS + 256;

    int tid = threadIdx.x;
    int wid = tid >> 5, lane = tid & 31;
    int wm = wid & 3, wn = wid >> 2;
    int n0 = blockIdx.x << 7;
    int mBase = blockIdx.y * (TPC * 128);
    int g = lane >> 2, cq = lane & 3;
    int mi = lane >> 3, l7 = lane & 7;

    int ROWT = tid >> 1, HALF = tid & 1;
    {
        const __nv_bfloat16* Bsrc = BT + (size_t)(n0 + ROWT) * 128 + HALF * 64;
        uint32_t Bdst = sBu + (ROWT * SR + HALF * 32) * 4;
        #pragma unroll
        for (int i = 0; i < 8; i++) cpa16(Bdst + i * 16, Bsrc + i * 8);
    }
    const __nv_bfloat16* AsrcB = A + (size_t)(mBase + ROWT) * 128 + HALF * 64;
    uint32_t AdstB = sAu + (ROWT * SR + HALF * 32) * 4;
    #pragma unroll
    for (int i = 0; i < 8; i++) cpa16(AdstB + i * 16, AsrcB + i * 8);
    asm volatile("cp.async.commit_group;" ::: "memory");

    uint32_t aRow[2], bRow[4];
    #pragma unroll
    for (int ma = 0; ma < 2; ma++)
        aRow[ma] = (uint32_t)((wm * 32 + ma * 16 + ((mi & 1) << 3) + l7) * SR +
                              ((mi >> 1) << 2)) * 4;
    #pragma unroll
    for (int np = 0; np < 4; np++)
        bRow[np] = (uint32_t)((wn * 64 + np * 16 + ((mi >> 1) << 3) + l7) * SR +
                              ((mi & 1) << 2)) * 4;

    asm volatile("cp.async.wait_group 0;" ::: "memory");
    __syncthreads();

    for (int t = 0; t < TPC; t++) {
        if (t + 1 < TPC) {
            const __nv_bfloat16* s = AsrcB + (size_t)(t + 1) * 128 * 128;
            uint32_t d = AdstB + ((t + 1) & 1) * TW * 4;
            #pragma unroll
            for (int i = 0; i < 8; i++) cpa16(d + i * 16, s + i * 8);
            asm volatile("cp.async.commit_group;" ::: "memory");
        }

        float acc[2][8][4];
        #pragma unroll
        for (int i = 0; i < 2; i++)
            #pragma unroll
            for (int j = 0; j < 8; j++)
                #pragma unroll
                for (int q = 0; q < 4; q++) acc[i][j][q] = 0.0f;
        MMA_PASS(sAu + (t & 1) * TW * 4, aRow, sBu, bRow, acc);

        int m0 = mBase + t * 128;

        if (EPI == 3) {
            int tok[2][2];
            #pragma unroll
            for (int ma = 0; ma < 2; ma++) {
                int rA = m0 + wm * 32 + ma * 16 + g;
                tok[ma][0] = img_of(rA);
                tok[ma][1] = img_of(rA + 8);
            }
            float sum[2][2] = {}, sq[2][2] = {};
            #pragma unroll
            for (int ma = 0; ma < 2; ma++)
                #pragma unroll
                for (int na = 0; na < 8; na++) {
                    int cb = n0 + wn * 64 + na * 8 + 2 * cq;
                    float b0 = bias[cb], b1 = bias[cb + 1];
                    float2 rA2 = *(const float2*)(res + (size_t)tok[ma][0] * DIM + cb);
                    float2 rB2 = *(const float2*)(res + (size_t)tok[ma][1] * DIM + cb);
                    float v0 = acc[ma][na][0] + b0 + rA2.x;
                    float v1 = acc[ma][na][1] + b1 + rA2.y;
                    float v2 = acc[ma][na][2] + b0 + rB2.x;
                    float v3 = acc[ma][na][3] + b1 + rB2.y;
                    acc[ma][na][0] = v0; acc[ma][na][1] = v1;
                    acc[ma][na][2] = v2; acc[ma][na][3] = v3;
                    sum[ma][0] += v0 + v1;  sq[ma][0] += v0 * v0 + v1 * v1;
                    sum[ma][1] += v2 + v3;  sq[ma][1] += v2 * v2 + v3 * v3;
                }
            #pragma unroll
            for (int ma = 0; ma < 2; ma++)
                #pragma unroll
                for (int rb = 0; rb < 2; rb++) {
                    sum[ma][rb] += __shfl_xor_sync(0xffffffffu, sum[ma][rb], 1);
                    sum[ma][rb] += __shfl_xor_sync(0xffffffffu, sum[ma][rb], 2);
                    sq[ma][rb]  += __shfl_xor_sync(0xffffffffu, sq[ma][rb], 1);
                    sq[ma][rb]  += __shfl_xor_sync(0xffffffffu, sq[ma][rb], 2);
                }
            if (cq == 0) {
                #pragma unroll
                for (int ma = 0; ma < 2; ma++)
                    #pragma unroll
                    for (int rb = 0; rb < 2; rb++) {
                        int rr = wm * 32 + ma * 16 + rb * 8 + g;
                        redS[wn * 128 + rr] = sum[ma][rb];
                        redQ[wn * 128 + rr] = sq[ma][rb];
                    }
            }
            __syncthreads();
            float mean[2][2], inv[2][2];
            #pragma unroll
            for (int ma = 0; ma < 2; ma++)
                #pragma unroll
                for (int rb = 0; rb < 2; rb++) {
                    int rr = wm * 32 + ma * 16 + rb * 8 + g;
                    float ts = redS[rr] + redS[128 + rr];
                    float tq = redQ[rr] + redQ[128 + rr];
                    float mn = ts * (1.0f / 128.0f);
                    float vr = tq * (1.0f / 128.0f) - mn * mn;
                    mean[ma][rb] = mn;
                    inv[ma][rb] = rsqrtf(vr + 1e-5f);
                }
            __nv_bfloat16* Cb = (__nv_bfloat16*)Cout;
            #pragma unroll
            for (int ma = 0; ma < 2; ma++)
                #pragma unroll
                for (int na = 0; na < 8; na++) {
                    int cb = n0 + wn * 64 + na * 8 + 2 * cq;
                    float w0 = lnw[cb], w1 = lnw[cb + 1];
                    float e0 = lnb[cb], e1 = lnb[cb + 1];
                    #pragma unroll
                    for (int rb = 0; rb < 2; rb++) {
                        int ti = tok[ma][rb];
                        float v0 = acc[ma][na][2 * rb], v1 = acc[ma][na][2 * rb + 1];
                        *(float2*)(out2 + (size_t)ti * DIM + cb) = make_float2(v0, v1);
                        float l0 = (v0 - mean[ma][rb]) * inv[ma][rb] * w0 + e0;
                        float l1 = (v1 - mean[ma][rb]) * inv[ma][rb] * w1 + e1;
                        *(__nv_bfloat162*)(Cb + (size_t)ti * DIM + cb) =
                            __floats2bfloat162_rn(l0, l1);
                    }
                }
        } else {
            #pragma unroll
            for (int ma = 0; ma < 2; ma++) {
                int r0 = m0 + wm * 32 + ma * 16 + g;
                #pragma unroll
                for (int na = 0; na < 8; na++) {
                    int cb = n0 + wn * 64 + na * 8 + 2 * cq;
                    float b0 = bias[cb], b1 = bias[cb + 1];
                    float v0 = acc[ma][na][0] + b0;
                    float v1 = acc[ma][na][1] + b1;
                    float v2 = acc[ma][na][2] + b0;
                    float v3 = acc[ma][na][3] + b1;
                    if (EPI == 1) {
                        v0 = 0.5f * v0 * (1.0f + erff(v0 * 0.7071067811865476f));
                        v1 = 0.5f * v1 * (1.0f + erff(v1 * 0.7071067811865476f));
                        v2 = 0.5f * v2 * (1.0f + erff(v2 * 0.7071067811865476f));
                        v3 = 0.5f * v3 * (1.0f + erff(v3 * 0.7071067811865476f));
                    }
                    __nv_bfloat16* Cb = (__nv_bfloat16*)Cout;
                    *(__nv_bfloat162*)(Cb + (size_t)r0 * N + cb) =
                        __floats2bfloat162_rn(v0, v1);
                    *(__nv_bfloat162*)(Cb + (size_t)(r0 + 8) * N + cb) =
                        __floats2bfloat162_rn(v2, v3);
                }
            }
        }

        if (t + 1 < TPC)
            asm volatile("cp.async.wait_group 0;" ::: "memory");
        __syncthreads();
    }
}

// -------- MLP2 GEMM (K=512, KC=64, double-buffered): +bias +residual -> fp32 --
__global__ void __launch_bounds__(256, 2)
k_bgemm2(const __nv_bfloat16* __restrict__ A, const __nv_bfloat16* __restrict__ BT,
         const float* __restrict__ bias, const float* __restrict__ res,
         float* __restrict__ Cout) {
    constexpr int SR = 36;                 // words per smem row (KC=64)
    constexpr int BUFW = 128 * SR;
    constexpr int K = 512, N = 128;
    extern __shared__ uint32_t dsm[];
    uint32_t sAu = smem_u32(dsm);
    uint32_t sBu = sAu + 2 * BUFW * 4;

    int tid = threadIdx.x;
    int wid = tid >> 5, lane = tid & 31;
    int wm = wid & 3, wn = wid >> 2;
    int m0 = blockIdx.y << 7, n0 = blockIdx.x << 7;
    int g = lane >> 2, cq = lane & 3;
    int mi = lane >> 3, l7 = lane & 7;

    float acc[2][8][4];
    #pragma unroll
    for (int i = 0; i < 2; i++)
        #pragma unroll
        for (int j = 0; j < 8; j++)
            #pragma unroll
            for (int q = 0; q < 4; q++) acc[i][j][q] = 0.0f;

    int ROWT = tid >> 1, HALF = tid & 1;
    const __nv_bfloat16* Asrc = A  + (size_t)(m0 + ROWT) * K + HALF * 32;
    const __nv_bfloat16* Bsrc = BT + (size_t)(n0 + ROWT) * K + HALF * 32;
    uint32_t Adst = sAu + (ROWT * SR + HALF * 16) * 4;
    uint32_t Bdst = sBu + (ROWT * SR + HALF * 16) * 4;

    uint32_t aRow[2], bRow[4];
    #pragma unroll
    for (int ma = 0; ma < 2; ma++)
        aRow[ma] = (uint32_t)((wm * 32 + ma * 16 + ((mi & 1) << 3) + l7) * SR +
                              ((mi >> 1) << 2)) * 4;
    #pragma unroll
    for (int np = 0; np < 4; np++)
        bRow[np] = (uint32_t)((wn * 64 + np * 16 + ((mi >> 1) << 3) + l7) * SR +
                              ((mi & 1) << 2)) * 4;

#define LOAD2(ch, b)                                                          \
    {                                                                         \
        _Pragma("unroll")                                                     \
        for (int i_ = 0; i_ < 4; i_++) {                                      \
            cpa16(Adst + (b) * BUFW * 4 + i_ * 16, Asrc + (ch) * 64 + i_ * 8); \
            cpa16(Bdst + (b) * BUFW * 4 + i_ * 16, Bsrc + (ch) * 64 + i_ * 8); \
        }                                                                     \
        asm volatile("cp.async.commit_group;" ::: "memory");                  \
    }
    LOAD2(0, 0);
    for (int ch = 0; ch < 8; ch++) {
        if (ch + 1 < 8) {
            LOAD2(ch + 1, (ch + 1) & 1);
            asm volatile("cp.async.wait_group 1;" ::: "memory");
        } else {
            asm volatile("cp.async.wait_group 0;" ::: "memory");
        }
        __syncthreads();
        uint32_t baseA = sAu + (ch & 1) * BUFW * 4;
        uint32_t baseB = sBu + (ch & 1) * BUFW * 4;
        #pragma unroll
        for (int ks = 0; ks < 4; ks++) {
            uint32_t kwb = (uint32_t)ks * 32;
            uint32_t a_[2][4], bb_[8][2];
            #pragma unroll
            for (int ma = 0; ma < 2; ma++)
                asm volatile(
                    "ldmatrix.sync.aligned.m8n8.x4.shared.b16 {%0,%1,%2,%3}, [%4];"
                    : "=r"(a_[ma][0]), "=r"(a_[ma][1]), "=r"(a_[ma][2]), "=r"(a_[ma][3])
                    : "r"(baseA + aRow[ma] + kwb));
            #pragma unroll
            for (int np = 0; np < 4; np++)
                asm volatile(
                    "ldmatrix.sync.aligned.m8n8.x4.shared.b16 {%0,%1,%2,%3}, [%4];"
                    : "=r"(bb_[2*np][0]), "=r"(bb_[2*np][1]),
                      "=r"(bb_[2*np+1][0]), "=r"(bb_[2*np+1][1])
                    : "r"(baseB + bRow[np] + kwb));
            #pragma unroll
            for (int ma = 0; ma < 2; ma++)
                #pragma unroll
                for (int na = 0; na < 8; na++)
                    asm volatile(
                        "mma.sync.aligned.m16n8k16.row.col.f32.bf16.bf16.f32 "
                        "{%0,%1,%2,%3}, {%4,%5,%6,%7}, {%8,%9}, {%0,%1,%2,%3};"
                        : "+f"(acc[ma][na][0]), "+f"(acc[ma][na][1]),
                          "+f"(acc[ma][na][2]), "+f"(acc[ma][na][3])
                        : "r"(a_[ma][0]), "r"(a_[ma][1]), "r"(a_[ma][2]), "r"(a_[ma][3]),
                          "r"(bb_[na][0]), "r"(bb_[na][1]));
        }
        __syncthreads();
    }
#undef LOAD2

    #pragma unroll
    for (int ma = 0; ma < 2; ma++) {
        int r0 = m0 + wm * 32 + ma * 16 + g;
        #pragma unroll
        for (int na = 0; na < 8; na++) {
            int cb = n0 + wn * 64 + na * 8 + 2 * cq;
            float b0 = bias[cb], b1 = bias[cb + 1];
            float2 r1v = *(const float2*)(res + (size_t)r0 * N + cb);
            float2 r2v = *(const float2*)(res + (size_t)(r0 + 8) * N + cb);
            *(float2*)(Cout + (size_t)r0 * N + cb) =
                make_float2(acc[ma][na][0] + b0 + r1v.x, acc[ma][na][1] + b1 + r1v.y);
            *(float2*)(Cout + (size_t)(r0 + 8) * N + cb) =
                make_float2(acc[ma][na][2] + b0 + r2v.x, acc[ma][na][3] + b1 + r2v.y);
        }
    }
}

// ------ kernel 3: tensor-core windowed attention, 4 heads per CTA ------------
#define AS 40   // bf16 row stride (= 20 words, conflict-free, 16B-aligned rows)
#define HEADB (64 * AS)            // bf16 elems per head per tensor
__device__ __forceinline__ int region_of(int p) {
    return p < Himg - WS ? 0 : (p < Himg - SHIFT ? 1 : 2);
}

__global__ void __launch_bounds__(512)
k_attn(const __nv_bfloat16* __restrict__ qkv, const float* __restrict__ rpb) {
    extern __shared__ char smc[];
    __nv_bfloat16* sQ = (__nv_bfloat16*)smc;             // [4][64*AS]
    __nv_bfloat16* sK = (__nv_bfloat16*)(smc + 20480);
    __nv_bfloat16* sV = (__nv_bfloat16*)(smc + 40960);
    float* sbAll = (float*)(smc + 61440);                // [4][169]

    int w = blockIdx.x;
    int tid = threadIdx.x;
    int h = tid >> 7;                  // head = warpgroup
    int wg = tid & 127;
    int wq = wg >> 5, lane = tid & 31;
    int g = lane >> 2, cq = lane & 3;
    int mi = lane >> 3, l7 = lane & 7;

    // fully-coalesced load: 48 x uint4 per token row, routed per head
    for (int i = tid; i < NTOK * 48; i += 512) {
        int t = i / 48, seg = i - t * 48;
        int z = seg >> 4, s = seg & 15;
        int hh = s >> 2, part = s & 3;
        const uint4* src = (const uint4*)(qkv + (size_t)(w * NTOK + t) * 384 +
                                          z * 128 + s * 8);
        __nv_bfloat16* dst = (z == 0 ? sQ : z == 1 ? sK : sV) +
                             hh * HEADB + t * AS + part * 8;
        *(uint4*)dst = *src;
    }
    for (int i = tid; i < 15 * 48; i += 512) {
        int t = NTOK + i / 48, seg = i % 48;
        int z = seg >> 4, s = seg & 15;
        int hh = s >> 2, part = s & 3;
        __nv_bfloat16* dst = (z == 0 ? sQ : z == 1 ? sK : sV) +
                             hh * HEADB + t * AS + part * 8;
        *(uint4*)dst = make_uint4(0, 0, 0, 0);
    }
    for (int i = tid; i < 676; i += 512)
        sbAll[(i & 3) * 169 + (i >> 2)] = rpb[i];
    __syncthreads();

    uint32_t squ = smem_u32(sQ + h * HEADB);
    uint32_t sku = smem_u32(sK + h * HEADB);
    uint32_t svu = smem_u32(sV + h * HEADB);
    const float* sb = sbAll + h * 169;

    uint32_t aBase = squ + (uint32_t)((wq * 16 + ((mi & 1) << 3) + l7) * 20 +
                                      ((mi >> 1) << 2)) * 4;
    uint32_t bBase[4];
    #pragma unroll
    for (int np = 0; np < 4; np++)
        bBase[np] = sku + (uint32_t)((np * 16 + ((mi >> 1) << 3) + l7) * 20 +
                                     ((mi & 1) << 2)) * 4;

    // QK^T
    float acc[8][4];
    #pragma unroll
    for (int na = 0; na < 8; na++)
        #pragma unroll
        for (int q2 = 0; q2 < 4; q2++) acc[na][q2] = 0.0f;
    #pragma unroll
    for (int kt = 0; kt < 2; kt++) {
        uint32_t a[4], bb[8][2];
        asm volatile("ldmatrix.sync.aligned.m8n8.x4.shared.b16 {%0,%1,%2,%3}, [%4];"
                     : "=r"(a[0]), "=r"(a[1]), "=r"(a[2]), "=r"(a[3])
                     : "r"(aBase + kt * 32));
        #pragma unroll
        for (int np = 0; np < 4; np++)
            asm volatile("ldmatrix.sync.aligned.m8n8.x4.shared.b16 {%0,%1,%2,%3}, [%4];"
                         : "=r"(bb[2*np][0]), "=r"(bb[2*np][1]),
                           "=r"(bb[2*np+1][0]), "=r"(bb[2*np+1][1])
                         : "r"(bBase[np] + kt * 32));
        #pragma unroll
        for (int na = 0; na < 8; na++)
            asm volatile(
                "mma.sync.aligned.m16n8k16.row.col.f32.bf16.bf16.f32 "
                "{%0,%1,%2,%3}, {%4,%5,%6,%7}, {%8,%9}, {%0,%1,%2,%3};"
                : "+f"(acc[na][0]), "+f"(acc[na][1]), "+f"(acc[na][2]), "+f"(acc[na][3])
                : "r"(a[0]), "r"(a[1]), "r"(a[2]), "r"(a[3]),
                  "r"(bb[na][0]), "r"(bb[na][1]));
    }

    int wi = w & 63, wy = wi >> 3, wx = wi & 7;
    bool ey = (wy == 7), ex = (wx == 7);
    const float scale = 0.17677669529663687f;
    int fm[14], rmv[14];
    #pragma unroll
    for (int na = 0; na < 7; na++)
        #pragma unroll
        for (int j = 0; j < 2; j++) {
            int m = 8 * na + 2 * cq + j;
            int mm = m < NTOK ? m : 0;
            int jy = mm / WS, jx = mm - jy * WS;
            fm[na * 2 + j] = jy * 13 + jx;
            int ry = ey ? (jy < 4 ? 1 : 2) : 0;
            int rx = ex ? (jx < 4 ? 1 : 2) : 0;
            rmv[na * 2 + j] = ry * 3 + rx;
        }
    bool v6 = (cq == 0);

    #pragma unroll
    for (int rb = 0; rb < 2; rb++) {
        int n = wq * 16 + rb * 8 + g;
        int nc = n < NTOK ? n : 0;
        int iy = nc / WS, ix = nc - iy * WS;
        int fn = iy * 13 + ix + 84;
        int rn = (ey ? (iy < 4 ? 1 : 2) : 0) * 3 + (ex ? (ix < 4 ? 1 : 2) : 0);
        float mx = -1e30f;
        #pragma unroll
        for (int na = 0; na < 8; na++)
            #pragma unroll
            for (int j = 0; j < 2; j++) {
                float s;
                if (na == 7) {
                    s = -30000.0f;
                } else {
                    int idx = na * 2 + j;
                    s = fmaf(acc[na][2 * rb + j], scale, sb[fn - fm[idx]]);
                    if (rn != rmv[idx]) s -= 100.0f;
                    if (na == 6 && !(v6 && j == 0)) s = -30000.0f;
                }
                acc[na][2 * rb + j] = s;
                mx = fmaxf(mx, s);
            }
        mx = fmaxf(mx, __shfl_xor_sync(0xffffffffu, mx, 1));
        mx = fmaxf(mx, __shfl_xor_sync(0xffffffffu, mx, 2));
        float sum = 0.0f;
        #pragma unroll
        for (int na = 0; na < 8; na++)
            #pragma unroll
            for (int j = 0; j < 2; j++) {
                float e = __expf(acc[na][2 * rb + j] - mx);
                acc[na][2 * rb + j] = e;
                sum += e;
            }
        sum += __shfl_xor_sync(0xffffffffu, sum, 1);
        sum += __shfl_xor_sync(0xffffffffu, sum, 2);
        float inv = 1.0f / sum;
        #pragma unroll
        for (int na = 0; na < 8; na++)
            #pragma unroll
            for (int j = 0; j < 2; j++) acc[na][2 * rb + j] *= inv;
    }

    // PV
    float acc2[4][4];
    #pragma unroll
    for (int nd = 0; nd < 4; nd++)
        #pragma unroll
        for (int q2 = 0; q2 < 4; q2++) acc2[nd][q2] = 0.0f;
    #pragma unroll
    for (int kt = 0; kt < 4; kt++) {
        uint32_t aP[4];
        __nv_bfloat162 p0 = __floats2bfloat162_rn(acc[2*kt][0],   acc[2*kt][1]);
        __nv_bfloat162 p1 = __floats2bfloat162_rn(acc[2*kt][2],   acc[2*kt][3]);
        __nv_bfloat162 p2 = __floats2bfloat162_rn(acc[2*kt+1][0], acc[2*kt+1][1]);
        __nv_bfloat162 p3 = __floats2bfloat162_rn(acc[2*kt+1][2], acc[2*kt+1][3]);
        aP[0] = *reinterpret_cast<uint32_t*>(&p0);
        aP[1] = *reinterpret_cast<uint32_t*>(&p1);
        aP[2] = *reinterpret_cast<uint32_t*>(&p2);
        aP[3] = *reinterpret_cast<uint32_t*>(&p3);
        uint32_t bv[4][2];
        #pragma unroll
        for (int dp = 0; dp < 2; dp++) {
            uint32_t addr = svu +
                (uint32_t)((16 * kt + ((mi & 1) << 3) + l7) * 20) * 4 +
                (uint32_t)((16 * dp + ((mi >> 1) << 3)) * 2);
            asm volatile("ldmatrix.sync.aligned.m8n8.x4.trans.shared.b16 {%0,%1,%2,%3}, [%4];"
                         : "=r"(bv[2*dp][0]), "=r"(bv[2*dp][1]),
                           "=r"(bv[2*dp+1][0]), "=r"(bv[2*dp+1][1])
                         : "r"(addr));
        }
        #pragma unroll
        for (int nd = 0; nd < 4; nd++)
            asm volatile(
                "mma.sync.aligned.m16n8k16.row.col.f32.bf16.bf16.f32 "
                "{%0,%1,%2,%3}, {%4,%5,%6,%7}, {%8,%9}, {%0,%1,%2,%3};"
                : "+f"(acc2[nd][0]), "+f"(acc2[nd][1]), "+f"(acc2[nd][2]), "+f"(acc2[nd][3])
                : "r"(aP[0]), "r"(aP[1]), "r"(aP[2]), "r"(aP[3]),
                  "r"(bv[nd][0]), "r"(bv[nd][1]));
    }

    #pragma unroll
    for (int rb = 0; rb < 2; rb++) {
        int n = wq * 16 + rb * 8 + g;
        if (n < NTOK) {
            #pragma unroll
            for (int nd = 0; nd < 4; nd++) {
                __nv_bfloat162 o = __floats2bfloat162_rn(acc2[nd][2*rb], acc2[nd][2*rb+1]);
                *(__nv_bfloat162*)(&g_attn[(size_t)(w * NTOK + n) * DIM + h * HD +
                                           8 * nd + 2 * cq]) = o;
            }
        }
    }
}

// ------------------------------- launcher ------------------------------------
extern "C" void kernel_launch(void* const* d_in, const int* in_sizes, int n_in,
                              void* d_out, int out_size) {
    const float* x      = (const float*)d_in[0];
    const float* qkv_w  = (const float*)d_in[1];
    const float* qkv_b  = (const float*)d_in[2];
    const float* proj_w = (const float*)d_in[3];
    const float* proj_b = (const float*)d_in[4];
    const float* rpb    = (const float*)d_in[5];
    const float* n1w    = (const float*)d_in[6];
    const float* n1b    = (const float*)d_in[7];
    const float* n2w    = (const float*)d_in[8];
    const float* n2b    = (const float*)d_in[9];
    const float* w1     = (const float*)d_in[10];
    const float* b1     = (const float*)d_in[11];
    const float* w2     = (const float*)d_in[12];
    const float* b2     = (const float*)d_in[13];
    float* out = (float*)d_out;

    __nv_bfloat16 *p_qkv, *p_attn, *p_ln2, *p_h, *p_wtq, *p_wtp, *p_wt1, *p_wt2;
    float *p_x2;
    cudaGetSymbolAddress((void**)&p_qkv,  g_qkv);
    cudaGetSymbolAddress((void**)&p_attn, g_attn);
    cudaGetSymbolAddress((void**)&p_x2,   g_x2);
    cudaGetSymbolAddress((void**)&p_ln2,  g_ln2);
    cudaGetSymbolAddress((void**)&p_h,    g_h);
    cudaGetSymbolAddress((void**)&p_wtq,  g_wt_qkv);
    cudaGetSymbolAddress((void**)&p_wtp,  g_wt_proj);
    cudaGetSymbolAddress((void**)&p_wt1,  g_wt1);
    cudaGetSymbolAddress((void**)&p_wt2,  g_wt2);

    const int dynQ = (2 * 128 * 68) * 4;                // 69632 B (k_qkv)
    const int dynP = (3 * 128 * 68 + 512) * 4;          // 106496 B (pipelined K=128)
    const int dyn2 = (2 * 2 * 128 * 36 + 512) * 4;      // 75776 B (MLP2)
    const int dynA = 61440 + 4 * 169 * 4;               // 64144 B (attention, 4 heads)
    cudaFuncSetAttribute(k_qkv<8>,       cudaFuncAttributeMaxDynamicSharedMemorySize, dynQ);
    cudaFuncSetAttribute(k_bgemm_p<1,8>, cudaFuncAttributeMaxDynamicSharedMemorySize, dynP);
    cudaFuncSetAttribute(k_bgemm_p<3,2>, cudaFuncAttributeMaxDynamicSharedMemorySize, dynP);
    cudaFuncSetAttribute(k_bgemm2,       cudaFuncAttributeMaxDynamicSharedMemorySize, dyn2);
    cudaFuncSetAttribute(k_attn,         cudaFuncAttributeMaxDynamicSharedMemorySize, dynA);

    // 0) fused weight transposes
    k_transpose_all<<<768, 256>>>(qkv_w, proj_w, w1, w2);

    // 1) QKV GEMM with fused LN1 + shift + window partition -> bf16
    k_qkv<8><<<dim3(3, MTOK / 128 / 8), 256, dynQ>>>(x, p_wtq, qkv_b, n1w, n1b, p_qkv);

    // 2) tensor-core windowed attention (4 heads per CTA) -> bf16
    k_attn<<<NWIN, 512, dynA>>>(p_qkv, rpb);

    // 3) proj GEMM + residual + window-reverse + LN2 (fused; TPC=2 for wave balance)
    k_bgemm_p<3,2><<<dim3(1, MTOK / 128 / 2), 256, dynP>>>(p_attn, p_wtp, proj_b, x,
                                                           p_ln2, 128, n2w, n2b, p_x2);

    // 4) MLP1 + GELU -> bf16 (pipelined over 8 M-tiles)
    k_bgemm_p<1,8><<<dim3(4, MTOK / 128 / 8), 256, dynP>>>(p_ln2, p_wt1, b1, nullptr,
                                                           p_h, 512, nullptr, nullptr, nullptr);

    // 5) MLP2 + bias + residual -> d_out fp32
    k_bgemm2<<<dim3(1, MTOK / 128), 256, dyn2>>>(p_h, p_wt2, b2, p_x2, out);
}

// round 13
// speedup vs baseline: 1.1438x; 1.1438x over previous
#include <cuda_runtime.h>
#include <cuda_bf16.h>
#include <math.h>
#include <stdint.h>

#define Himg 56
#define Wimg 56
#define WS 7
#define SHIFT 3
#define HEADS 4
#define DIM 128
#define NTOK 49
#define NWIN 4096           // 64 imgs * 64 windows
#define MTOK 200704         // NWIN * NTOK
#define HD 32

// ---------------- scratch (static device globals; no allocation) -------------
// qkv layout: [z][h][token][32]  (z = q/k/v, h = head)  -- head-major
__device__ __nv_bfloat16 g_qkv [(size_t)12 * MTOK * 32];
__device__ __nv_bfloat16 g_attn[(size_t)MTOK * DIM];
__device__ float         g_x2  [(size_t)MTOK * DIM];
__device__ __nv_bfloat16 g_ln2 [(size_t)MTOK * DIM];
__device__ __nv_bfloat16 g_h   [(size_t)MTOK * 4 * DIM];
// transposed weights [N, K] in bf16
__device__ __nv_bfloat16 g_wt_qkv [384 * 128];
__device__ __nv_bfloat16 g_wt_proj[128 * 128];
__device__ __nv_bfloat16 g_wt1    [512 * 128];
__device__ __nv_bfloat16 g_wt2    [128 * 512];

__device__ __forceinline__ uint32_t smem_u32(const void* p) {
    uint32_t a;
    asm("{ .reg .u64 t; cvta.to.shared.u64 t, %1; cvt.u32.u64 %0, t; }" : "=r"(a) : "l"(p));
    return a;
}
__device__ __forceinline__ void cpa16(uint32_t dst, const void* src) {
    asm volatile("cp.async.cg.shared.global [%0], [%1], 16;" :: "r"(dst), "l"(src));
}
__device__ __forceinline__ int img_of(int wt) {
    int w = wt / NTOK, n = wt - w * NTOK;
    int bimg = w >> 6, wi = w & 63;
    int rr = (wi >> 3) * WS + n / WS;
    int cc = (wi & 7)  * WS + n % WS;
    int r = rr + SHIFT; if (r >= Himg) r -= Himg;
    int c = cc + SHIFT; if (c >= Wimg) c -= Wimg;
    return bimg * 3136 + r * 56 + c;
}

// ---------------- kernel 0: all 4 weight transposes fused ---------------------
__global__ void k_transpose_all(const float* __restrict__ qkv_w,
                                const float* __restrict__ proj_w,
                                const float* __restrict__ w1,
                                const float* __restrict__ w2) {
    int i = blockIdx.x * 256 + threadIdx.x;
    if (i < 49152) {
        int k = i / 384, n = i - k * 384;
        g_wt_qkv[n * 128 + k] = __float2bfloat16(qkv_w[i]);
    } else if (i < 65536) {
        int j = i - 49152;
        int k = j >> 7, n = j & 127;
        g_wt_proj[n * 128 + k] = __float2bfloat16(proj_w[j]);
    } else if (i < 131072) {
        int j = i - 65536;
        int k = j >> 9, n = j & 511;
        g_wt1[n * 128 + k] = __float2bfloat16(w1[j]);
    } else if (i < 196608) {
        int j = i - 131072;
        int k = j >> 7, n = j & 127;
        g_wt2[n * 512 + k] = __float2bfloat16(w2[j]);
    }
}

// ---- shared MMA pass macro: 128x128 output tile, K=128, over 8 k-steps ------
#define MMA_PASS(baseA, aR, baseB, bR, ACC)                                   \
    {                                                                         \
        _Pragma("unroll")                                                     \
        for (int ks = 0; ks < 8; ks++) {                                      \
            uint32_t kwb = (uint32_t)ks * 32;                                 \
            uint32_t a_[2][4], bb_[8][2];                                     \
            _Pragma("unroll")                                                 \
            for (int ma = 0; ma < 2; ma++)                                    \
                asm volatile(                                                 \
                    "ldmatrix.sync.aligned.m8n8.x4.shared.b16 {%0,%1,%2,%3}, [%4];" \
                    : "=r"(a_[ma][0]), "=r"(a_[ma][1]), "=r"(a_[ma][2]), "=r"(a_[ma][3]) \
                    : "r"((baseA) + aR[ma] + kwb));                           \
            _Pragma("unroll")                                                 \
            for (int np = 0; np < 4; np++)                                    \
                asm volatile(                                                 \
                    "ldmatrix.sync.aligned.m8n8.x4.shared.b16 {%0,%1,%2,%3}, [%4];" \
                    : "=r"(bb_[2*np][0]), "=r"(bb_[2*np][1]),                 \
                      "=r"(bb_[2*np+1][0]), "=r"(bb_[2*np+1][1])              \
                    : "r"((baseB) + bR[np] + kwb));                           \
            _Pragma("unroll")                                                 \
            for (int ma = 0; ma < 2; ma++)                                    \
                _Pragma("unroll")                                             \
                for (int na = 0; na < 8; na++)                                \
                    asm volatile(                                             \
                        "mma.sync.aligned.m16n8k16.row.col.f32.bf16.bf16.f32 " \
                        "{%0,%1,%2,%3}, {%4,%5,%6,%7}, {%8,%9}, {%0,%1,%2,%3};" \
                        : "+f"(ACC[ma][na][0]), "+f"(ACC[ma][na][1]),         \
                          "+f"(ACC[ma][na][2]), "+f"(ACC[ma][na][3])          \
                        : "r"(a_[ma][0]), "r"(a_[ma][1]), "r"(a_[ma][2]), "r"(a_[ma][3]), \
                          "r"(bb_[na][0]), "r"(bb_[na][1]));                  \
        }                                                                     \
    }

// ---- QKV GEMM with FUSED LN1 + shift + window-partition on the A path -------
// Output written head-major: g_qkv[(z*4+h)*MTOK + token][32]
template <int TPC>
__global__ void __launch_bounds__(256, 2)
k_qkv(const float* __restrict__ x, const __nv_bfloat16* __restrict__ BT,
      const float* __restrict__ bias,
      const float* __restrict__ gw, const float* __restrict__ gb,
      __nv_bfloat16* __restrict__ C) {
    constexpr int SR = 68;
    constexpr int TW = 128 * SR;
    extern __shared__ uint32_t dsm[];
    uint32_t sBu = smem_u32(dsm);              // B tile (resident)
    uint32_t* sA = dsm + TW;                   // A tile (LN-filled)
    uint32_t sAu = sBu + TW * 4;

    int tid = threadIdx.x;
    int wid = tid >> 5, lane = tid & 31;
    int wm = wid & 3, wn = wid >> 2;
    int n0 = blockIdx.x << 7;
    int zz = blockIdx.x;                       // q/k/v slab
    int mBase = blockIdx.y * (TPC * 128);
    int g = lane >> 2, cq = lane & 3;
    int mi = lane >> 3, l7 = lane & 7;

    {
        int ROWT = tid >> 1, HALF = tid & 1;
        const __nv_bfloat16* Bsrc = BT + (size_t)(n0 + ROWT) * 128 + HALF * 64;
        uint32_t Bdst = sBu + (ROWT * SR + HALF * 32) * 4;
        #pragma unroll
        for (int i = 0; i < 8; i++) cpa16(Bdst + i * 16, Bsrc + i * 8);
        asm volatile("cp.async.commit_group;" ::: "memory");
    }

    float4 w4 = *(const float4*)(gw + lane * 4);
    float4 b4 = *(const float4*)(gb + lane * 4);

    uint32_t aRow[2], bRow[4];
    #pragma unroll
    for (int ma = 0; ma < 2; ma++)
        aRow[ma] = (uint32_t)((wm * 32 + ma * 16 + ((mi & 1) << 3) + l7) * SR +
                              ((mi >> 1) << 2)) * 4;
    #pragma unroll
    for (int np = 0; np < 4; np++)
        bRow[np] = (uint32_t)((wn * 64 + np * 16 + ((mi >> 1) << 3) + l7) * SR +
                              ((mi & 1) << 2)) * 4;

    for (int t = 0; t < TPC; t++) {
        int m0 = mBase + t * 128;
        #pragma unroll
        for (int grp = 0; grp < 4; grp++) {
            float4 v[4];
            int rows[4];
            #pragma unroll
            for (int r = 0; r < 4; r++) {
                rows[r] = wid * 16 + grp * 4 + r;
                int img = img_of(m0 + rows[r]);
                v[r] = *(const float4*)(x + (size_t)img * DIM + lane * 4);
            }
            #pragma unroll
            for (int r = 0; r < 4; r++) {
                float sv = v[r].x + v[r].y + v[r].z + v[r].w;
                float sq = v[r].x * v[r].x + v[r].y * v[r].y +
                           v[r].z * v[r].z + v[r].w * v[r].w;
                #pragma unroll
                for (int o = 16; o > 0; o >>= 1) {
                    sv += __shfl_xor_sync(0xffffffffu, sv, o);
                    sq += __shfl_xor_sync(0xffffffffu, sq, o);
                }
                float mean = sv * (1.0f / 128.0f);
                float inv  = rsqrtf(sq * (1.0f / 128.0f) - mean * mean + 1e-5f);
                __nv_bfloat162 o0 = __floats2bfloat162_rn(
                    (v[r].x - mean) * inv * w4.x + b4.x,
                    (v[r].y - mean) * inv * w4.y + b4.y);
                __nv_bfloat162 o1 = __floats2bfloat162_rn(
                    (v[r].z - mean) * inv * w4.z + b4.z,
                    (v[r].w - mean) * inv * w4.w + b4.w);
                uint2 pk;
                pk.x = *reinterpret_cast<uint32_t*>(&o0);
                pk.y = *reinterpret_cast<uint32_t*>(&o1);
                *(uint2*)(sA + rows[r] * SR + lane * 2) = pk;
            }
        }
        if (t == 0)
            asm volatile("cp.async.wait_group 0;" ::: "memory");
        __syncthreads();

        float acc[2][8][4];
        #pragma unroll
        for (int i = 0; i < 2; i++)
            #pragma unroll
            for (int j = 0; j < 8; j++)
                #pragma unroll
                for (int q = 0; q < 4; q++) acc[i][j][q] = 0.0f;
        MMA_PASS(sAu, aRow, sBu, bRow, acc);

        #pragma unroll
        for (int ma = 0; ma < 2; ma++) {
            int r0 = m0 + wm * 32 + ma * 16 + g;
            #pragma unroll
            for (int na = 0; na < 8; na++) {
                int col = wn * 64 + na * 8 + 2 * cq;   // 0..126 within slab
                int cb = n0 + col;
                float b0 = bias[cb], b1 = bias[cb + 1];
                int hh = col >> 5, dd = col & 31;
                size_t base = ((size_t)(zz * 4 + hh) * MTOK);
                *(__nv_bfloat162*)(C + (base + r0) * 32 + dd) =
                    __floats2bfloat162_rn(acc[ma][na][0] + b0, acc[ma][na][1] + b1);
                *(__nv_bfloat162*)(C + (base + r0 + 8) * 32 + dd) =
                    __floats2bfloat162_rn(acc[ma][na][2] + b0, acc[ma][na][3] + b1);
            }
        }
        __syncthreads();
    }
}

// ---- M-tile-pipelined bf16 HMMA GEMM, K=128, B tile resident ----------------
// EPI: 1 = +bias, GELU (bf16 out);
//      3 = +bias +residual[x, scattered] + LN2 -> ln2 bf16 (Cout) + x2 fp32 (out2)
template <int EPI, int TPC>
__global__ void __launch_bounds__(256, 2)
k_bgemm_p(const __nv_bfloat16* __restrict__ A, const __nv_bfloat16* __restrict__ BT,
          const float* __restrict__ bias, const float* __restrict__ res,
          void* __restrict__ Cout, int N,
          const float* __restrict__ lnw, const float* __restrict__ lnb,
          float* __restrict__ out2) {
    constexpr int SR = 68;                     // words per smem row
    constexpr int TW = 128 * SR;
    extern __shared__ uint32_t dsm[];
    uint32_t sBu = smem_u32(dsm);              // B tile (resident)
    uint32_t sAu = sBu + TW * 4;               // A tiles (double buffer)
    float* redS = (float*)(dsm + 3 * TW);
    float* redQ = redS + 256;

    int tid = threadIdx.x;
    int wid = tid >> 5, lane = tid & 31;
    int wm = wid & 3, wn = wid >> 2;
    int n0 = blockIdx.x << 7;
    int mBase = blockIdx.y * (TPC * 128);
    int g = lane >> 2, cq = lane & 3;
    int mi = lane >> 3, l7 = lane & 7;

    int ROWT = tid >> 1, HALF = tid & 1;
    {
        const __nv_bfloat16* Bsrc = BT + (size_t)(n0 + ROWT) * 128 + HALF * 64;
        uint32_t Bdst = sBu + (ROWT * SR + HALF * 32) * 4;
        #pragma unroll
        for (int i = 0; i < 8; i++) cpa16(Bdst + i * 16, Bsrc + i * 8);
    }
    const __nv_bfloat16* AsrcB = A + (size_t)(mBase + ROWT) * 128 + HALF * 64;
    uint32_t AdstB = sAu + (ROWT * SR + HALF * 32) * 4;
    #pragma unroll
    for (int i = 0; i < 8; i++) cpa16(AdstB + i * 16, AsrcB + i * 8);
    asm volatile("cp.async.commit_group;" ::: "memory");

    uint32_t aRow[2], bRow[4];
    #pragma unroll
    for (int ma = 0; ma < 2; ma++)
        aRow[ma] = (uint32_t)((wm * 32 + ma * 16 + ((mi & 1) << 3) + l7) * SR +
                              ((mi >> 1) << 2)) * 4;
    #pragma unroll
    for (int np = 0; np < 4; np++)
        bRow[np] = (uint32_t)((wn * 64 + np * 16 + ((mi >> 1) << 3) + l7) * SR +
                              ((mi & 1) << 2)) * 4;

    asm volatile("cp.async.wait_group 0;" ::: "memory");
    __syncthreads();

    for (int t = 0; t < TPC; t++) {
        if (t + 1 < TPC) {
            const __nv_bfloat16* s = AsrcB + (size_t)(t + 1) * 128 * 128;
            uint32_t d = AdstB + ((t + 1) & 1) * TW * 4;
            #pragma unroll
            for (int i = 0; i < 8; i++) cpa16(d + i * 16, s + i * 8);
            asm volatile("cp.async.commit_group;" ::: "memory");
        }

        float acc[2][8][4];
        #pragma unroll
        for (int i = 0; i < 2; i++)
            #pragma unroll
            for (int j = 0; j < 8; j++)
                #pragma unroll
                for (int q = 0; q < 4; q++) acc[i][j][q] = 0.0f;
        MMA_PASS(sAu + (t & 1) * TW * 4, aRow, sBu, bRow, acc);

        int m0 = mBase + t * 128;

        if (EPI == 3) {
            int tok[2][2];
            #pragma unroll
            for (int ma = 0; ma < 2; ma++) {
                int rA = m0 + wm * 32 + ma * 16 + g;
                tok[ma][0] = img_of(rA);
                tok[ma][1] = img_of(rA + 8);
            }
            float sum[2][2] = {}, sq[2][2] = {};
            #pragma unroll
            for (int ma = 0; ma < 2; ma++)
                #pragma unroll
                for (int na = 0; na < 8; na++) {
                    int cb = n0 + wn * 64 + na * 8 + 2 * cq;
                    float b0 = bias[cb], b1 = bias[cb + 1];
                    float2 rA2 = *(const float2*)(res + (size_t)tok[ma][0] * DIM + cb);
                    float2 rB2 = *(const float2*)(res + (size_t)tok[ma][1] * DIM + cb);
                    float v0 = acc[ma][na][0] + b0 + rA2.x;
                    float v1 = acc[ma][na][1] + b1 + rA2.y;
                    float v2 = acc[ma][na][2] + b0 + rB2.x;
                    float v3 = acc[ma][na][3] + b1 + rB2.y;
                    acc[ma][na][0] = v0; acc[ma][na][1] = v1;
                    acc[ma][na][2] = v2; acc[ma][na][3] = v3;
                    sum[ma][0] += v0 + v1;  sq[ma][0] += v0 * v0 + v1 * v1;
                    sum[ma][1] += v2 + v3;  sq[ma][1] += v2 * v2 + v3 * v3;
                }
            #pragma unroll
            for (int ma = 0; ma < 2; ma++)
                #pragma unroll
                for (int rb = 0; rb < 2; rb++) {
                    sum[ma][rb] += __shfl_xor_sync(0xffffffffu, sum[ma][rb], 1);
                    sum[ma][rb] += __shfl_xor_sync(0xffffffffu, sum[ma][rb], 2);
                    sq[ma][rb]  += __shfl_xor_sync(0xffffffffu, sq[ma][rb], 1);
                    sq[ma][rb]  += __shfl_xor_sync(0xffffffffu, sq[ma][rb], 2);
                }
            if (cq == 0) {
                #pragma unroll
                for (int ma = 0; ma < 2; ma++)
                    #pragma unroll
                    for (int rb = 0; rb < 2; rb++) {
                        int rr = wm * 32 + ma * 16 + rb * 8 + g;
                        redS[wn * 128 + rr] = sum[ma][rb];
                        redQ[wn * 128 + rr] = sq[ma][rb];
                    }
            }
            __syncthreads();
            float mean[2][2], inv[2][2];
            #pragma unroll
            for (int ma = 0; ma < 2; ma++)
                #pragma unroll
                for (int rb = 0; rb < 2; rb++) {
                    int rr = wm * 32 + ma * 16 + rb * 8 + g;
                    float ts = redS[rr] + redS[128 + rr];
                    float tq = redQ[rr] + redQ[128 + rr];
                    float mn = ts * (1.0f / 128.0f);
                    float vr = tq * (1.0f / 128.0f) - mn * mn;
                    mean[ma][rb] = mn;
                    inv[ma][rb] = rsqrtf(vr + 1e-5f);
                }
            __nv_bfloat16* Cb = (__nv_bfloat16*)Cout;
            #pragma unroll
            for (int ma = 0; ma < 2; ma++)
                #pragma unroll
                for (int na = 0; na < 8; na++) {
                    int cb = n0 + wn * 64 + na * 8 + 2 * cq;
                    float w0 = lnw[cb], w1 = lnw[cb + 1];
                    float e0 = lnb[cb], e1 = lnb[cb + 1];
                    #pragma unroll
                    for (int rb = 0; rb < 2; rb++) {
                        int ti = tok[ma][rb];
                        float v0 = acc[ma][na][2 * rb], v1 = acc[ma][na][2 * rb + 1];
                        *(float2*)(out2 + (size_t)ti * DIM + cb) = make_float2(v0, v1);
                        float l0 = (v0 - mean[ma][rb]) * inv[ma][rb] * w0 + e0;
                        float l1 = (v1 - mean[ma][rb]) * inv[ma][rb] * w1 + e1;
                        *(__nv_bfloat162*)(Cb + (size_t)ti * DIM + cb) =
                            __floats2bfloat162_rn(l0, l1);
                    }
                }
        } else {
            #pragma unroll
            for (int ma = 0; ma < 2; ma++) {
                int r0 = m0 + wm * 32 + ma * 16 + g;
                #pragma unroll
                for (int na = 0; na < 8; na++) {
                    int cb = n0 + wn * 64 + na * 8 + 2 * cq;
                    float b0 = bias[cb], b1 = bias[cb + 1];
                    float v0 = acc[ma][na][0] + b0;
                    float v1 = acc[ma][na][1] + b1;
                    float v2 = acc[ma][na][2] + b0;
                    float v3 = acc[ma][na][3] + b1;
                    if (EPI == 1) {
                        v0 = 0.5f * v0 * (1.0f + erff(v0 * 0.7071067811865476f));
                        v1 = 0.5f * v1 * (1.0f + erff(v1 * 0.7071067811865476f));
                        v2 = 0.5f * v2 * (1.0f + erff(v2 * 0.7071067811865476f));
                        v3 = 0.5f * v3 * (1.0f + erff(v3 * 0.7071067811865476f));
                    }
                    __nv_bfloat16* Cb = (__nv_bfloat16*)Cout;
                    *(__nv_bfloat162*)(Cb + (size_t)r0 * N + cb) =
                        __floats2bfloat162_rn(v0, v1);
                    *(__nv_bfloat162*)(Cb + (size_t)(r0 + 8) * N + cb) =
                        __floats2bfloat162_rn(v2, v3);
                }
            }
        }

        if (t + 1 < TPC)
            asm volatile("cp.async.wait_group 0;" ::: "memory");
        __syncthreads();
    }
}

// -------- MLP2 GEMM (K=512, KC=64, double-buffered): +bias +residual -> fp32 --
__global__ void __launch_bounds__(256, 2)
k_bgemm2(const __nv_bfloat16* __restrict__ A, const __nv_bfloat16* __restrict__ BT,
         const float* __restrict__ bias, const float* __restrict__ res,
         float* __restrict__ Cout) {
    constexpr int SR = 36;                 // words per smem row (KC=64)
    constexpr int BUFW = 128 * SR;
    constexpr int K = 512, N = 128;
    extern __shared__ uint32_t dsm[];
    uint32_t sAu = smem_u32(dsm);
    uint32_t sBu = sAu + 2 * BUFW * 4;

    int tid = threadIdx.x;
    int wid = tid >> 5, lane = tid & 31;
    int wm = wid & 3, wn = wid >> 2;
    int m0 = blockIdx.y << 7, n0 = blockIdx.x << 7;
    int g = lane >> 2, cq = lane & 3;
    int mi = lane >> 3, l7 = lane & 7;

    float acc[2][8][4];
    #pragma unroll
    for (int i = 0; i < 2; i++)
        #pragma unroll
        for (int j = 0; j < 8; j++)
            #pragma unroll
            for (int q = 0; q < 4; q++) acc[i][j][q] = 0.0f;

    int ROWT = tid >> 1, HALF = tid & 1;
    const __nv_bfloat16* Asrc = A  + (size_t)(m0 + ROWT) * K + HALF * 32;
    const __nv_bfloat16* Bsrc = BT + (size_t)(n0 + ROWT) * K + HALF * 32;
    uint32_t Adst = sAu + (ROWT * SR + HALF * 16) * 4;
    uint32_t Bdst = sBu + (ROWT * SR + HALF * 16) * 4;

    uint32_t aRow[2], bRow[4];
    #pragma unroll
    for (int ma = 0; ma < 2; ma++)
        aRow[ma] = (uint32_t)((wm * 32 + ma * 16 + ((mi & 1) << 3) + l7) * SR +
                              ((mi >> 1) << 2)) * 4;
    #pragma unroll
    for (int np = 0; np < 4; np++)
        bRow[np] = (uint32_t)((wn * 64 + np * 16 + ((mi >> 1) << 3) + l7) * SR +
                              ((mi & 1) << 2)) * 4;

#define LOAD2(ch, b)                                                          \
    {                                                                         \
        _Pragma("unroll")                                                     \
        for (int i_ = 0; i_ < 4; i_++) {                                      \
            cpa16(Adst + (b) * BUFW * 4 + i_ * 16, Asrc + (ch) * 64 + i_ * 8); \
            cpa16(Bdst + (b) * BUFW * 4 + i_ * 16, Bsrc + (ch) * 64 + i_ * 8); \
        }                                                                     \
        asm volatile("cp.async.commit_group;" ::: "memory");                  \
    }
    LOAD2(0, 0);
    for (int ch = 0; ch < 8; ch++) {
        if (ch + 1 < 8) {
            LOAD2(ch + 1, (ch + 1) & 1);
            asm volatile("cp.async.wait_group 1;" ::: "memory");
        } else {
            asm volatile("cp.async.wait_group 0;" ::: "memory");
        }
        __syncthreads();
        uint32_t baseA = sAu + (ch & 1) * BUFW * 4;
        uint32_t baseB = sBu + (ch & 1) * BUFW * 4;
        #pragma unroll
        for (int ks = 0; ks < 4; ks++) {
            uint32_t kwb = (uint32_t)ks * 32;
            uint32_t a_[2][4], bb_[8][2];
            #pragma unroll
            for (int ma = 0; ma < 2; ma++)
                asm volatile(
                    "ldmatrix.sync.aligned.m8n8.x4.shared.b16 {%0,%1,%2,%3}, [%4];"
                    : "=r"(a_[ma][0]), "=r"(a_[ma][1]), "=r"(a_[ma][2]), "=r"(a_[ma][3])
                    : "r"(baseA + aRow[ma] + kwb));
            #pragma unroll
            for (int np = 0; np < 4; np++)
                asm volatile(
                    "ldmatrix.sync.aligned.m8n8.x4.shared.b16 {%0,%1,%2,%3}, [%4];"
                    : "=r"(bb_[2*np][0]), "=r"(bb_[2*np][1]),
                      "=r"(bb_[2*np+1][0]), "=r"(bb_[2*np+1][1])
                    : "r"(baseB + bRow[np] + kwb));
            #pragma unroll
            for (int ma = 0; ma < 2; ma++)
                #pragma unroll
                for (int na = 0; na < 8; na++)
                    asm volatile(
                        "mma.sync.aligned.m16n8k16.row.col.f32.bf16.bf16.f32 "
                        "{%0,%1,%2,%3}, {%4,%5,%6,%7}, {%8,%9}, {%0,%1,%2,%3};"
                        : "+f"(acc[ma][na][0]), "+f"(acc[ma][na][1]),
                          "+f"(acc[ma][na][2]), "+f"(acc[ma][na][3])
                        : "r"(a_[ma][0]), "r"(a_[ma][1]), "r"(a_[ma][2]), "r"(a_[ma][3]),
                          "r"(bb_[na][0]), "r"(bb_[na][1]));
        }
        __syncthreads();
    }
#undef LOAD2

    #pragma unroll
    for (int ma = 0; ma < 2; ma++) {
        int r0 = m0 + wm * 32 + ma * 16 + g;
        #pragma unroll
        for (int na = 0; na < 8; na++) {
            int cb = n0 + wn * 64 + na * 8 + 2 * cq;
            float b0 = bias[cb], b1 = bias[cb + 1];
            float2 r1v = *(const float2*)(res + (size_t)r0 * N + cb);
            float2 r2v = *(const float2*)(res + (size_t)(r0 + 8) * N + cb);
            *(float2*)(Cout + (size_t)r0 * N + cb) =
                make_float2(acc[ma][na][0] + b0 + r1v.x, acc[ma][na][1] + b1 + r1v.y);
            *(float2*)(Cout + (size_t)(r0 + 8) * N + cb) =
                make_float2(acc[ma][na][2] + b0 + r2v.x, acc[ma][na][3] + b1 + r2v.y);
        }
    }
}

// ---------------- kernel 3: tensor-core windowed attention -------------------
#define AS 40   // bf16 row stride (= 20 words, conflict-free, 16B-aligned rows)
__device__ __forceinline__ int region_of(int p) {
    return p < Himg - WS ? 0 : (p < Himg - SHIFT ? 1 : 2);
}

__global__ void __launch_bounds__(128)
k_attn(const __nv_bfloat16* __restrict__ qkv, const float* __restrict__ rpb) {
    __shared__ __align__(16) __nv_bfloat16 sq[64 * AS], sk[64 * AS], sv[64 * AS];
    __shared__ float sb[169];
    int w = blockIdx.x, h = blockIdx.y;
    int tid = threadIdx.x, wq = tid >> 5, lane = tid & 31;
    int g = lane >> 2, cq = lane & 3;
    int mi = lane >> 3, l7 = lane & 7;

    // head-major qkv: slab (z*4+h), contiguous 49*32 bf16 per (w,z,h)
    for (int i = tid; i < NTOK * 12; i += 128) {
        int z = i / (NTOK * 4);
        int rem = i - z * (NTOK * 4);
        int t = rem >> 2, part = rem & 3;
        const uint4* src = (const uint4*)(qkv +
            ((size_t)(z * 4 + h) * MTOK + (size_t)w * NTOK + t) * 32 + part * 8);
        __nv_bfloat16* dst = (z == 0 ? sq : z == 1 ? sk : sv) + t * AS + part * 8;
        *(uint4*)dst = *src;
    }
    for (int i = tid; i < 15 * 12; i += 128) {
        int t = NTOK + i / 12, rem = i % 12, z = rem >> 2, part = rem & 3;
        __nv_bfloat16* dst = (z == 0 ? sq : z == 1 ? sk : sv) + t * AS + part * 8;
        *(uint4*)dst = make_uint4(0, 0, 0, 0);
    }
    for (int i = tid; i < 169; i += 128) sb[i] = rpb[i * 4 + h];
    __syncthreads();

    uint32_t squ = smem_u32(sq), sku = smem_u32(sk), svu = smem_u32(sv);
    uint32_t aBase = squ + (uint32_t)((wq * 16 + ((mi & 1) << 3) + l7) * 20 +
                                      ((mi >> 1) << 2)) * 4;
    uint32_t bBase[4];
    #pragma unroll
    for (int np = 0; np < 4; np++)
        bBase[np] = sku + (uint32_t)((np * 16 + ((mi >> 1) << 3) + l7) * 20 +
                                     ((mi & 1) << 2)) * 4;

    float acc[8][4];
    #pragma unroll
    for (int na = 0; na < 8; na++)
        #pragma unroll
        for (int q2 = 0; q2 < 4; q2++) acc[na][q2] = 0.0f;
    #pragma unroll
    for (int kt = 0; kt < 2; kt++) {
        uint32_t a[4], bb[8][2];
        asm volatile("ldmatrix.sync.aligned.m8n8.x4.shared.b16 {%0,%1,%2,%3}, [%4];"
                     : "=r"(a[0]), "=r"(a[1]), "=r"(a[2]), "=r"(a[3])
                     : "r"(aBase + kt * 32));
        #pragma unroll
        for (int np = 0; np < 4; np++)
            asm volatile("ldmatrix.sync.aligned.m8n8.x4.shared.b16 {%0,%1,%2,%3}, [%4];"
                         : "=r"(bb[2*np][0]), "=r"(bb[2*np][1]),
                           "=r"(bb[2*np+1][0]), "=r"(bb[2*np+1][1])
                         : "r"(bBase[np] + kt * 32));
        #pragma unroll
        for (int na = 0; na < 8; na++)
            asm volatile(
                "mma.sync.aligned.m16n8k16.row.col.f32.bf16.bf16.f32 "
                "{%0,%1,%2,%3}, {%4,%5,%6,%7}, {%8,%9}, {%0,%1,%2,%3};"
                : "+f"(acc[na][0]), "+f"(acc[na][1]), "+f"(acc[na][2]), "+f"(acc[na][3])
                : "r"(a[0]), "r"(a[1]), "r"(a[2]), "r"(a[3]),
                  "r"(bb[na][0]), "r"(bb[na][1]));
    }

    int wi = w & 63, wy = wi >> 3, wx = wi & 7;
    bool ey = (wy == 7), ex = (wx == 7);
    const float scale = 0.17677669529663687f;
    int fm[14], rmv[14];
    #pragma unroll
    for (int na = 0; na < 7; na++)
        #pragma unroll
        for (int j = 0; j < 2; j++) {
            int m = 8 * na + 2 * cq + j;
            int mm = m < NTOK ? m : 0;
            int jy = mm / WS, jx = mm - jy * WS;
            fm[na * 2 + j] = jy * 13 + jx;
            int ry = ey ? (jy < 4 ? 1 : 2) : 0;
            int rx = ex ? (jx < 4 ? 1 : 2) : 0;
            rmv[na * 2 + j] = ry * 3 + rx;
        }
    bool v6 = (cq == 0);

    #pragma unroll
    for (int rb = 0; rb < 2; rb++) {
        int n = wq * 16 + rb * 8 + g;
        int nc = n < NTOK ? n : 0;
        int iy = nc / WS, ix = nc - iy * WS;
        int fn = iy * 13 + ix + 84;
        int rn = (ey ? (iy < 4 ? 1 : 2) : 0) * 3 + (ex ? (ix < 4 ? 1 : 2) : 0);
        float mx = -1e30f;
        #pragma unroll
        for (int na = 0; na < 8; na++)
            #pragma unroll
            for (int j = 0; j < 2; j++) {
                float s;
                if (na == 7) {
                    s = -30000.0f;
                } else {
                    int idx = na * 2 + j;
                    s = fmaf(acc[na][2 * rb + j], scale, sb[fn - fm[idx]]);
                    if (rn != rmv[idx]) s -= 100.0f;
                    if (na == 6 && !(v6 && j == 0)) s = -30000.0f;
                }
                acc[na][2 * rb + j] = s;
                mx = fmaxf(mx, s);
            }
        mx = fmaxf(mx, __shfl_xor_sync(0xffffffffu, mx, 1));
        mx = fmaxf(mx, __shfl_xor_sync(0xffffffffu, mx, 2));
        float sum = 0.0f;
        #pragma unroll
        for (int na = 0; na < 8; na++)
            #pragma unroll
            for (int j = 0; j < 2; j++) {
                float e = __expf(acc[na][2 * rb + j] - mx);
                acc[na][2 * rb + j] = e;
                sum += e;
            }
        sum += __shfl_xor_sync(0xffffffffu, sum, 1);
        sum += __shfl_xor_sync(0xffffffffu, sum, 2);
        float inv = 1.0f / sum;
        #pragma unroll
        for (int na = 0; na < 8; na++)
            #pragma unroll
            for (int j = 0; j < 2; j++) acc[na][2 * rb + j] *= inv;
    }

    float acc2[4][4];
    #pragma unroll
    for (int nd = 0; nd < 4; nd++)
        #pragma unroll
        for (int q2 = 0; q2 < 4; q2++) acc2[nd][q2] = 0.0f;
    #pragma unroll
    for (int kt = 0; kt < 4; kt++) {
        uint32_t aP[4];
        __nv_bfloat162 p0 = __floats2bfloat162_rn(acc[2*kt][0],   acc[2*kt][1]);
        __nv_bfloat162 p1 = __floats2bfloat162_rn(acc[2*kt][2],   acc[2*kt][3]);
        __nv_bfloat162 p2 = __floats2bfloat162_rn(acc[2*kt+1][0], acc[2*kt+1][1]);
        __nv_bfloat162 p3 = __floats2bfloat162_rn(acc[2*kt+1][2], acc[2*kt+1][3]);
        aP[0] = *reinterpret_cast<uint32_t*>(&p0);
        aP[1] = *reinterpret_cast<uint32_t*>(&p1);
        aP[2] = *reinterpret_cast<uint32_t*>(&p2);
        aP[3] = *reinterpret_cast<uint32_t*>(&p3);
        uint32_t bv[4][2];
        #pragma unroll
        for (int dp = 0; dp < 2; dp++) {
            uint32_t addr = svu +
                (uint32_t)((16 * kt + ((mi & 1) << 3) + l7) * 20) * 4 +
                (uint32_t)((16 * dp + ((mi >> 1) << 3)) * 2);
            asm volatile("ldmatrix.sync.aligned.m8n8.x4.trans.shared.b16 {%0,%1,%2,%3}, [%4];"
                         : "=r"(bv[2*dp][0]), "=r"(bv[2*dp][1]),
                           "=r"(bv[2*dp+1][0]), "=r"(bv[2*dp+1][1])
                         : "r"(addr));
        }
        #pragma unroll
        for (int nd = 0; nd < 4; nd++)
            asm volatile(
                "mma.sync.aligned.m16n8k16.row.col.f32.bf16.bf16.f32 "
                "{%0,%1,%2,%3}, {%4,%5,%6,%7}, {%8,%9}, {%0,%1,%2,%3};"
                : "+f"(acc2[nd][0]), "+f"(acc2[nd][1]), "+f"(acc2[nd][2]), "+f"(acc2[nd][3])
                : "r"(aP[0]), "r"(aP[1]), "r"(aP[2]), "r"(aP[3]),
                  "r"(bv[nd][0]), "r"(bv[nd][1]));
    }

    #pragma unroll
    for (int rb = 0; rb < 2; rb++) {
        int n = wq * 16 + rb * 8 + g;
        if (n < NTOK) {
            #pragma unroll
            for (int nd = 0; nd < 4; nd++) {
                __nv_bfloat162 o = __floats2bfloat162_rn(acc2[nd][2*rb], acc2[nd][2*rb+1]);
                *(__nv_bfloat162*)(&g_attn[(size_t)(w * NTOK + n) * DIM + h * HD +
                                           8 * nd + 2 * cq]) = o;
            }
        }
    }
}

// ------------------------------- launcher ------------------------------------
extern "C" void kernel_launch(void* const* d_in, const int* in_sizes, int n_in,
                              void* d_out, int out_size) {
    const float* x      = (const float*)d_in[0];
    const float* qkv_w  = (const float*)d_in[1];
    const float* qkv_b  = (const float*)d_in[2];
    const float* proj_w = (const float*)d_in[3];
    const float* proj_b = (const float*)d_in[4];
    const float* rpb    = (const float*)d_in[5];
    const float* n1w    = (const float*)d_in[6];
    const float* n1b    = (const float*)d_in[7];
    const float* n2w    = (const float*)d_in[8];
    const float* n2b    = (const float*)d_in[9];
    const float* w1     = (const float*)d_in[10];
    const float* b1     = (const float*)d_in[11];
    const float* w2     = (const float*)d_in[12];
    const float* b2     = (const float*)d_in[13];
    float* out = (float*)d_out;

    __nv_bfloat16 *p_qkv, *p_attn, *p_ln2, *p_h, *p_wtq, *p_wtp, *p_wt1, *p_wt2;
    float *p_x2;
    cudaGetSymbolAddress((void**)&p_qkv,  g_qkv);
    cudaGetSymbolAddress((void**)&p_attn, g_attn);
    cudaGetSymbolAddress((void**)&p_x2,   g_x2);
    cudaGetSymbolAddress((void**)&p_ln2,  g_ln2);
    cudaGetSymbolAddress((void**)&p_h,    g_h);
    cudaGetSymbolAddress((void**)&p_wtq,  g_wt_qkv);
    cudaGetSymbolAddress((void**)&p_wtp,  g_wt_proj);
    cudaGetSymbolAddress((void**)&p_wt1,  g_wt1);
    cudaGetSymbolAddress((void**)&p_wt2,  g_wt2);

    const int dynQ = (2 * 128 * 68) * 4;                // 69632 B (k_qkv)
    const int dynP = (3 * 128 * 68 + 512) * 4;          // 106496 B (pipelined K=128)
    const int dyn2 = (2 * 2 * 128 * 36 + 512) * 4;      // 75776 B (MLP2)
    cudaFuncSetAttribute(k_qkv<8>,       cudaFuncAttributeMaxDynamicSharedMemorySize, dynQ);
    cudaFuncSetAttribute(k_bgemm_p<1,8>, cudaFuncAttributeMaxDynamicSharedMemorySize, dynP);
    cudaFuncSetAttribute(k_bgemm_p<3,4>, cudaFuncAttributeMaxDynamicSharedMemorySize, dynP);
    cudaFuncSetAttribute(k_bgemm2,       cudaFuncAttributeMaxDynamicSharedMemorySize, dyn2);

    // 0) fused weight transposes
    k_transpose_all<<<768, 256>>>(qkv_w, proj_w, w1, w2);

    // 1) QKV GEMM with fused LN1 + shift + window partition -> bf16 (head-major)
    k_qkv<8><<<dim3(3, MTOK / 128 / 8), 256, dynQ>>>(x, p_wtq, qkv_b, n1w, n1b, p_qkv);

    // 2) tensor-core windowed attention -> bf16
    k_attn<<<dim3(NWIN, HEADS), 128>>>(p_qkv, rpb);

    // 3) proj GEMM + residual + window-reverse + LN2 (fused; pipelined over 4 M-tiles)
    k_bgemm_p<3,4><<<dim3(1, MTOK / 128 / 4), 256, dynP>>>(p_attn, p_wtp, proj_b, x,
                                                           p_ln2, 128, n2w, n2b, p_x2);

    // 4) MLP1 + GELU -> bf16 (pipelined over 8 M-tiles)
    k_bgemm_p<1,8><<<dim3(4, MTOK / 128 / 8), 256, dynP>>>(p_ln2, p_wt1, b1, nullptr,
                                                           p_h, 512, nullptr, nullptr, nullptr);

    // 5) MLP2 + bias + residual -> d_out fp32
    k_bgemm2<<<dim3(1, MTOK / 128), 256, dyn2>>>(p_h, p_wt2, b2, p_x2, out);
}